// round 11
// baseline (speedup 1.0000x reference)
#include <cuda_runtime.h>
#include <cuda_fp16.h>
#include <math.h>
#include <stdint.h>

// ---------------- problem constants ----------------
#define D       256
#define K2      512           // small-kernel contraction (u|v form)
#define KP      1024          // TC contraction: 4 children x 256
#define KCH     64            // K per TC iteration
#define NITER   (KP / KCH)    // 16
#define LEVELS  9
#define MAX_PAR 16384
#define NLEAF   65536

// ---------------- device scratch (no cudaMalloc allowed) ----------------
__device__ float  g_h[2][(size_t)MAX_PAR * D];          // fp32 ping-pong (small levels + bridge)
__device__ float  g_WcT[(size_t)K2 * D];                // fp32 W for small kernel
__device__ __half g_lh_h[(size_t)NLEAF * D];            // leaf h split hi
__device__ __half g_lh_l[(size_t)NLEAF * D];            // leaf h split lo
__device__ __half g_ph_h[2][(size_t)MAX_PAR * D];       // TC-output h split hi (ping-pong)
__device__ __half g_ph_l[2][(size_t)MAX_PAR * D];       // TC-output h split lo
__device__ __half g_Bh[(size_t)NITER * 2 * 128 * KCH];  // pre-swizzled B-hi chunk images
__device__ __half g_Bl[(size_t)NITER * 2 * 128 * KCH];  // pre-swizzled B-lo chunk images

// ---------------- helpers ----------------
__device__ __forceinline__ uint32_t smem_u32(const void* p) {
    uint32_t a;
    asm("{ .reg .u64 t; cvta.to.shared.u64 t, %1; cvt.u32.u64 %0, t; }"
        : "=r"(a) : "l"(p));
    return a;
}
#define SW128(o) ((o) ^ (((o) >> 3) & 0x70))

__device__ __forceinline__ void cp16(uint32_t dst, const void* src) {
    asm volatile("cp.async.cg.shared.global [%0], [%1], 16;"
                 :: "r"(dst), "l"(src) : "memory");
}
#define CP_COMMIT() asm volatile("cp.async.commit_group;" ::: "memory")
#define CP_WAIT0()  asm volatile("cp.async.wait_group 0;" ::: "memory")

#define LDSM4(r, addr) \
    asm volatile("ldmatrix.sync.aligned.m8n8.x4.shared.b16 {%0,%1,%2,%3}, [%4];" \
        : "=r"((r)[0]), "=r"((r)[1]), "=r"((r)[2]), "=r"((r)[3]) : "r"(addr))

#define MMA16816(c, a, b0_, b1_) \
    asm volatile("mma.sync.aligned.m16n8k16.row.col.f32.f16.f16.f32 " \
        "{%0,%1,%2,%3}, {%4,%5,%6,%7}, {%8,%9}, {%0,%1,%2,%3};" \
        : "+f"((c)[0]), "+f"((c)[1]), "+f"((c)[2]), "+f"((c)[3]) \
        : "r"((a)[0]), "r"((a)[1]), "r"((a)[2]), "r"((a)[3]), "r"(b0_), "r"(b1_))

// ---------------- pack W (transposed fp32) for small kernel ----------------
__global__ void __launch_bounds__(256)
pack_w_kernel(const float* __restrict__ Wl, const float* __restrict__ Wr) {
    __shared__ float t[32][33];
    const float* src = blockIdx.z ? Wr : Wl;
    int i0 = blockIdx.x * 32;
    int k0 = blockIdx.y * 32;
    int lx = threadIdx.x, ly = threadIdx.y;
#pragma unroll
    for (int r = 0; r < 4; r++)
        t[ly + 8 * r][lx] = src[(size_t)(i0 + ly + 8 * r) * D + k0 + lx];
    __syncthreads();
#pragma unroll
    for (int r = 0; r < 4; r++) {
        int k = k0 + ly + 8 * r + (blockIdx.z ? D : 0);
        g_WcT[(size_t)k * D + i0 + lx] = t[lx][ly + 8 * r];
    }
}

// ---------------- pack coefficient-folded B (fp16 hi/lo, pre-swizzled) ----
// Bt[n][kk] = lc_j*Wl[n][k] + rc_j*Wr[n][k], kk = j*256+k.
// Image (iter, n-half): [128 rows][64 cols] fp16, SW128-swizzled.
__global__ void __launch_bounds__(256)
pack_b_kernel(const float* __restrict__ Wl, const float* __restrict__ Wr) {
    int gid = blockIdx.x * 256 + threadIdx.x;     // over 256*1024
    int n = gid >> 10;
    int kk = gid & 1023;
    int j = kk >> 8;
    int k = kk & 255;
    const float C13 = 1.0f / 3.0f, C23 = 2.0f / 3.0f;
    float lc = (j == 0) ? 1.0f : (j == 1) ? C23 : (j == 2) ? C13 : 0.0f;
    float rc = (j == 0) ? 0.0f : (j == 1) ? C13 : (j == 2) ? C23 : 1.0f;
    float w = lc * Wl[(size_t)n * D + k] + rc * Wr[(size_t)n * D + k];
    __half hi = __float2half_rn(w);
    __half lo = __float2half_rn(w - __half2float(hi));
    int it = kk >> 6;
    int c = kk & 63;
    int nh = n >> 7;
    int r = n & 127;
    size_t off = (size_t)(it * 2 + nh) * 8192 + (SW128(r * 128 + c * 2) >> 1);
    g_Bh[off] = hi;
    g_Bl[off] = lo;
}

// ---------------- leaf split: fp32 -> fp16 hi/lo ----------------
__global__ void __launch_bounds__(256)
leaf_split_kernel(const float* __restrict__ v) {
    size_t b = ((size_t)blockIdx.x * 256 + threadIdx.x) * 8;
    float4 x0 = *reinterpret_cast<const float4*>(v + b);
    float4 x1 = *reinterpret_cast<const float4*>(v + b + 4);
    float xs[8] = {x0.x, x0.y, x0.z, x0.w, x1.x, x1.y, x1.z, x1.w};
    union { __half h[8]; uint4 u; } hh, hl;
#pragma unroll
    for (int e = 0; e < 8; e++) {
        __half hi = __float2half_rn(xs[e]);
        hh.h[e] = hi;
        hl.h[e] = __float2half_rn(xs[e] - __half2float(hi));
    }
    *reinterpret_cast<uint4*>(g_lh_h + b) = hh.u;
    *reinterpret_cast<uint4*>(g_lh_l + b) = hl.u;
}

// ---------------- TC GEMM: 3xFP16 split via mma.sync ----------------
// CTA: 128 parents x 128 cols, grid (n_par/128, 2). K=1024, chunks of 64.
// smem per buffer: Ah 16K | Al 16K | Bh 16K | Bl 16K = 64K; double buffered.
#define SMB 65536

struct TcArgs {
    const __half* hh;
    const __half* hl;
    int pbase, nh, kc;
};

__device__ __forceinline__ void tc_produce(uint32_t dst, int tid, const TcArgs& a) {
#pragma unroll
    for (int t = 0; t < 4; t++) {
        int G = tid + t * 256;
        int r = G >> 3, cg = G & 7;
        size_t so = (size_t)(a.pbase + r) * KP + a.kc + cg * 8;
        uint32_t d = dst + SW128(r * 128 + cg * 16);
        cp16(d, a.hh + so);
        cp16(d + 16384, a.hl + so);
    }
    int it = a.kc / KCH;
    const __half* bh = g_Bh + (size_t)(it * 2 + a.nh) * 8192;
    const __half* bl = g_Bl + (size_t)(it * 2 + a.nh) * 8192;
#pragma unroll
    for (int t = 0; t < 4; t++) {
        int G = tid + t * 256;
        uint32_t d = dst + 32768 + G * 16;
        cp16(d, bh + G * 8);
        cp16(d + 16384, bl + G * 8);
    }
    CP_COMMIT();
}

__global__ void __launch_bounds__(256)
gemm_tc_kernel(const __half* __restrict__ hhin, const __half* __restrict__ hlin,
               const float* __restrict__ bias,
               float* __restrict__ h32, __half* __restrict__ hho,
               __half* __restrict__ hlo) {
    extern __shared__ __align__(1024) char smem[];
    const uint32_t sb = smem_u32(smem);
    const int tid = threadIdx.x;
    const int lane = tid & 31;
    const int wid = tid >> 5;
    const int wm = wid & 1;          // M half (0/1 -> 64 rows)
    const int wn = wid >> 1;         // N quarter (0..3 -> 32 cols)
    const int pbase = blockIdx.x * 128;
    const int nh = blockIdx.y;

    float acc[4][4][4];
#pragma unroll
    for (int mt = 0; mt < 4; mt++)
#pragma unroll
        for (int nt = 0; nt < 4; nt++)
#pragma unroll
            for (int e = 0; e < 4; e++) acc[mt][nt][e] = 0.0f;

    TcArgs args = {hhin, hlin, pbase, nh, 0};
    tc_produce(sb, tid, args);

    // per-lane ldmatrix address components
    const int arow = (lane >> 3 & 1) * 8 + (lane & 7);     // A: +8 rows by grp&1
    const int acol = (lane >> 4) * 16;                     // A: +8 k (bytes) by grp>>1
    const int brow = (lane >> 4) * 8 + (lane & 7);         // B: +8 rows by grp>>1
    const int bcol = (lane >> 3 & 1) * 16;                 // B: +8 k by grp&1

    for (int i = 0; i < NITER; i++) {
        CP_WAIT0();
        __syncthreads();
        if (i + 1 < NITER) {
            args.kc = (i + 1) * KCH;
            tc_produce(sb + ((i + 1) & 1) * SMB, tid, args);
        }
        const uint32_t s0 = sb + (i & 1) * SMB;

#pragma unroll
        for (int ks = 0; ks < 4; ks++) {
            uint32_t ah[4][4], al[4][4];
#pragma unroll
            for (int mt = 0; mt < 4; mt++) {
                int row = wm * 64 + mt * 16 + arow;
                uint32_t ad = s0 + SW128(row * 128 + ks * 32 + acol);
                LDSM4(ah[mt], ad);
                LDSM4(al[mt], ad + 16384);
            }
            uint32_t bh[2][4], bl[2][4];
#pragma unroll
            for (int ntp = 0; ntp < 2; ntp++) {
                int row = wn * 32 + ntp * 16 + brow;
                uint32_t bd = s0 + 32768 + SW128(row * 128 + ks * 32 + bcol);
                LDSM4(bh[ntp], bd);
                LDSM4(bl[ntp], bd + 16384);
            }
#pragma unroll
            for (int mt = 0; mt < 4; mt++)
#pragma unroll
                for (int nt = 0; nt < 4; nt++) {
                    int np = nt >> 1, sel = (nt & 1) * 2;
                    MMA16816(acc[mt][nt], ah[mt], bh[np][sel], bh[np][sel + 1]);
                    MMA16816(acc[mt][nt], ah[mt], bl[np][sel], bl[np][sel + 1]);
                    MMA16816(acc[mt][nt], al[mt], bh[np][sel], bh[np][sel + 1]);
                }
        }
    }

    // ---- epilogue: bias + tanh; write fp32 h and fp16 hi/lo split ----
#pragma unroll
    for (int mt = 0; mt < 4; mt++) {
#pragma unroll
        for (int nt = 0; nt < 4; nt++) {
            int p0 = pbase + wm * 64 + mt * 16 + (lane >> 2);
            int nn = nh * 128 + wn * 32 + nt * 8 + 2 * (lane & 3);
#pragma unroll
            for (int half = 0; half < 2; half++) {
                int p = p0 + half * 8;
                size_t o = (size_t)p * D + nn;
                float2 bv = *reinterpret_cast<const float2*>(bias + o);
                float v0 = tanhf(acc[mt][nt][half * 2 + 0] + bv.x);
                float v1 = tanhf(acc[mt][nt][half * 2 + 1] + bv.y);
                float2 ov = {v0, v1};
                *reinterpret_cast<float2*>(h32 + o) = ov;
                __half h0 = __float2half_rn(v0);
                __half h1 = __float2half_rn(v1);
                *reinterpret_cast<__half2*>(hho + o) = __halves2half2(h0, h1);
                __half l0 = __float2half_rn(v0 - __half2float(h0));
                __half l1 = __float2half_rn(v1 - __half2float(h1));
                *reinterpret_cast<__half2*>(hlo + o) = __halves2half2(l0, l1);
            }
        }
    }
}

// ---------------- small-level kernel (fp32, K-split across warps) --------
#define PT 8
__global__ void __launch_bounds__(256)
gemm_small_kernel(const float* __restrict__ hin, const float* __restrict__ bias,
                  float* __restrict__ hout, int n_par) {
    __shared__ float uv_s[PT][K2];
    __shared__ float part[8][PT][32];

    const int tid = threadIdx.x;
    const int pbase = blockIdx.x * PT;
    const int col0 = blockIdx.y * 32;
    const float C13 = 1.0f / 3.0f;
    const float C23 = 2.0f / 3.0f;

#pragma unroll
    for (int i = 0; i < PT * K2 / 256; i++) {
        int idx = tid + i * 256;
        int lp = idx >> 9;
        int k = idx & 511;
        int c = k & 255;
        int p = pbase + lp;
        float v = 0.0f;
        if (p < n_par) {
            const float* cb = hin + ((size_t)p * 4) * D + c;
            if (k < D) v = cb[0] + C23 * cb[D] + C13 * cb[2 * D];
            else       v = C13 * cb[D] + C23 * cb[2 * D] + cb[3 * D];
        }
        uv_s[lp][k] = v;
    }
    __syncthreads();

    const int w = tid >> 5;
    const int lane = tid & 31;
    const float* wp = g_WcT + (size_t)(w * 64) * D + col0 + lane;

    float acc[PT];
#pragma unroll
    for (int p = 0; p < PT; p++) acc[p] = 0.0f;

#pragma unroll 8
    for (int k = 0; k < 64; k++) {
        float wv = wp[(size_t)k * D];
        int kg = w * 64 + k;
#pragma unroll
        for (int p = 0; p < PT; p++)
            acc[p] = fmaf(uv_s[p][kg], wv, acc[p]);
    }
#pragma unroll
    for (int p = 0; p < PT; p++) part[w][p][lane] = acc[p];
    __syncthreads();

    int p = tid >> 5;
    int pg = pbase + p;
    if (pg < n_par) {
        float s = 0.0f;
#pragma unroll
        for (int w2 = 0; w2 < 8; w2++) s += part[w2][p][lane];
        int n = col0 + lane;
        hout[(size_t)pg * D + n] = tanhf(s + bias[(size_t)pg * D + n]);
    }
}

// ---------------- host launcher ------------------------------------------
extern "C" void kernel_launch(void* const* d_in, const int* in_sizes, int n_in,
                              void* d_out, int out_size) {
    const float* vectors = (const float*)d_in[0];
    const float* Wl      = (const float*)d_in[1];
    const float* Wr      = (const float*)d_in[2];
    float* out = (float*)d_out;

    static bool attr_set = false;
    if (!attr_set) {
        cudaFuncSetAttribute(gemm_tc_kernel,
                             cudaFuncAttributeMaxDynamicSharedMemorySize, 2 * SMB);
        attr_set = true;
    }

    int offsets[LEVELS];
    int s = 0, sz = 1;
    for (int l = 0; l < LEVELS; l++) { offsets[l] = s; s += sz; sz *= 4; }

    float* hbuf;
    cudaGetSymbolAddress((void**)&hbuf, g_h);
    float* hb[2] = {hbuf, hbuf + (size_t)MAX_PAR * D};

    __half *phh, *phl, *lhh, *lhl;
    cudaGetSymbolAddress((void**)&phh, g_ph_h);
    cudaGetSymbolAddress((void**)&phl, g_ph_l);
    cudaGetSymbolAddress((void**)&lhh, g_lh_h);
    cudaGetSymbolAddress((void**)&lhl, g_lh_l);
    __half* ph_h[2] = {phh, phh + (size_t)MAX_PAR * D};
    __half* ph_l[2] = {phl, phl + (size_t)MAX_PAR * D};

    pack_w_kernel<<<dim3(8, 8, 2), dim3(32, 8)>>>(Wl, Wr);
    pack_b_kernel<<<1024, 256>>>(Wl, Wr);
    leaf_split_kernel<<<NLEAF * D / (256 * 8), 256>>>(
        vectors + (size_t)offsets[LEVELS - 1] * D);

    const __half* hh_in = lhh;
    const __half* hl_in = lhl;
    const float* h32_in = nullptr;
    int n_par = 1 << (2 * (LEVELS - 2));   // 16384

    for (int l = LEVELS - 2; l >= 0; l--) {
        const float* bias = vectors + (size_t)offsets[l] * D;
        if (n_par >= 1024) {
            float* h32o = hb[l & 1];
            gemm_tc_kernel<<<dim3(n_par / 128, 2), 256, 2 * SMB>>>(
                hh_in, hl_in, bias, h32o, ph_h[l & 1], ph_l[l & 1]);
            hh_in = ph_h[l & 1];
            hl_in = ph_l[l & 1];
            h32_in = h32o;
        } else {
            float* hout = (l == 0) ? out : hb[l & 1];
            dim3 grid((n_par + PT - 1) / PT, 8);
            gemm_small_kernel<<<grid, 256>>>(h32_in, bias, hout, n_par);
            h32_in = hout;
        }
        n_par >>= 2;
    }
}

// round 13
// speedup vs baseline: 1.1927x; 1.1927x over previous
#include <cuda_runtime.h>
#include <cuda_fp16.h>
#include <math.h>
#include <stdint.h>

// ---------------- problem constants ----------------
#define D       256
#define K2      512           // small-kernel contraction (u|v form)
#define KP      1024          // TC contraction: 4 children x 256
#define KCH     64            // K per TC iteration
#define NITER   (KP / KCH)    // 16
#define LEVELS  9
#define MAX_PAR 16384
#define NLEAF   65536

// ---------------- device scratch (no cudaMalloc allowed) ----------------
__device__ float  g_h[2][(size_t)MAX_PAR * D];          // fp32 ping-pong (small levels)
__device__ float  g_WcT[(size_t)K2 * D];                // fp32 W for small kernel
__device__ __half g_lh_h[(size_t)NLEAF * D];            // leaf h split hi
__device__ __half g_lh_l[(size_t)NLEAF * D];            // leaf h split lo
__device__ __half g_ph_h[2][(size_t)MAX_PAR * D];       // TC-output h split hi (ping-pong)
__device__ __half g_ph_l[2][(size_t)MAX_PAR * D];       // TC-output h split lo
__device__ __half g_Bh[(size_t)NITER * 256 * KCH];      // pre-swizzled B-hi iter images
__device__ __half g_Bl[(size_t)NITER * 256 * KCH];      // pre-swizzled B-lo iter images

// ---------------- helpers ----------------
__device__ __forceinline__ uint32_t smem_u32(const void* p) {
    uint32_t a;
    asm("{ .reg .u64 t; cvta.to.shared.u64 t, %1; cvt.u32.u64 %0, t; }"
        : "=r"(a) : "l"(p));
    return a;
}
#define SW128(o) ((o) ^ (((o) >> 3) & 0x70))

__device__ __forceinline__ void cp16(uint32_t dst, const void* src) {
    asm volatile("cp.async.cg.shared.global [%0], [%1], 16;"
                 :: "r"(dst), "l"(src) : "memory");
}
#define CP_COMMIT() asm volatile("cp.async.commit_group;" ::: "memory")
#define CP_WAIT0()  asm volatile("cp.async.wait_group 0;" ::: "memory")

#define LDSM4(r, addr) \
    asm volatile("ldmatrix.sync.aligned.m8n8.x4.shared.b16 {%0,%1,%2,%3}, [%4];" \
        : "=r"((r)[0]), "=r"((r)[1]), "=r"((r)[2]), "=r"((r)[3]) : "r"(addr))

#define MMA16816(c, a, b0_, b1_) \
    asm volatile("mma.sync.aligned.m16n8k16.row.col.f32.f16.f16.f32 " \
        "{%0,%1,%2,%3}, {%4,%5,%6,%7}, {%8,%9}, {%0,%1,%2,%3};" \
        : "+f"((c)[0]), "+f"((c)[1]), "+f"((c)[2]), "+f"((c)[3]) \
        : "r"((a)[0]), "r"((a)[1]), "r"((a)[2]), "r"((a)[3]), "r"(b0_), "r"(b1_))

// ---------------- pack W (transposed fp32) for small kernel ----------------
__global__ void __launch_bounds__(256)
pack_w_kernel(const float* __restrict__ Wl, const float* __restrict__ Wr) {
    __shared__ float t[32][33];
    const float* src = blockIdx.z ? Wr : Wl;
    int i0 = blockIdx.x * 32;
    int k0 = blockIdx.y * 32;
    int lx = threadIdx.x, ly = threadIdx.y;
#pragma unroll
    for (int r = 0; r < 4; r++)
        t[ly + 8 * r][lx] = src[(size_t)(i0 + ly + 8 * r) * D + k0 + lx];
    __syncthreads();
#pragma unroll
    for (int r = 0; r < 4; r++) {
        int k = k0 + ly + 8 * r + (blockIdx.z ? D : 0);
        g_WcT[(size_t)k * D + i0 + lx] = t[lx][ly + 8 * r];
    }
}

// ---------------- pack coefficient-folded B (fp16 hi/lo, pre-swizzled) ----
// Bt[n][kk] = lc_j*Wl[n][k] + rc_j*Wr[n][k], kk = j*256+k.
// Image per iter: [256 rows(n)][64 cols] fp16, SW128-swizzled, 32KB.
__global__ void __launch_bounds__(256)
pack_b_kernel(const float* __restrict__ Wl, const float* __restrict__ Wr) {
    int gid = blockIdx.x * 256 + threadIdx.x;     // over 256*1024
    int n = gid >> 10;
    int kk = gid & 1023;
    int j = kk >> 8;
    int k = kk & 255;
    const float C13 = 1.0f / 3.0f, C23 = 2.0f / 3.0f;
    float lc = (j == 0) ? 1.0f : (j == 1) ? C23 : (j == 2) ? C13 : 0.0f;
    float rc = (j == 0) ? 0.0f : (j == 1) ? C13 : (j == 2) ? C23 : 1.0f;
    float w = lc * Wl[(size_t)n * D + k] + rc * Wr[(size_t)n * D + k];
    __half hi = __float2half_rn(w);
    __half lo = __float2half_rn(w - __half2float(hi));
    int it = kk >> 6;
    int c = kk & 63;
    size_t off = (size_t)it * 16384 + (SW128(n * 128 + c * 2) >> 1);
    g_Bh[off] = hi;
    g_Bl[off] = lo;
}

// ---------------- leaf split: fp32 -> fp16 hi/lo ----------------
__global__ void __launch_bounds__(256)
leaf_split_kernel(const float* __restrict__ v) {
    size_t b = ((size_t)blockIdx.x * 256 + threadIdx.x) * 8;
    float4 x0 = *reinterpret_cast<const float4*>(v + b);
    float4 x1 = *reinterpret_cast<const float4*>(v + b + 4);
    float xs[8] = {x0.x, x0.y, x0.z, x0.w, x1.x, x1.y, x1.z, x1.w};
    union { __half h[8]; uint4 u; } hh, hl;
#pragma unroll
    for (int e = 0; e < 8; e++) {
        __half hi = __float2half_rn(xs[e]);
        hh.h[e] = hi;
        hl.h[e] = __float2half_rn(xs[e] - __half2float(hi));
    }
    *reinterpret_cast<uint4*>(g_lh_h + b) = hh.u;
    *reinterpret_cast<uint4*>(g_lh_l + b) = hl.u;
}

// ---------------- TC GEMM: 3xFP16 split via mma.sync ----------------
// CTA: MROWS(=MT*32) parents x 256 cols, 512 threads (16 warps: 2M x 8N,
// warp tile MT*16 x 32). K=1024, chunks of 64, double-buffered cp.async.
// smem buffer: Ahi 16K | Alo 16K | Bhi 32K | Blo 32K = 96K; x2 = 192K.
#define SMB 98304

template<int MT, bool WRITE32, bool WRITE16>
__global__ void __launch_bounds__(512)
gemm_tc_kernel(const __half* __restrict__ hhin, const __half* __restrict__ hlin,
               const float* __restrict__ bias,
               float* __restrict__ h32, __half* __restrict__ hho,
               __half* __restrict__ hlo) {
    constexpr int MROWS = MT * 32;
    extern __shared__ __align__(1024) char smem[];
    const uint32_t sb = smem_u32(smem);
    const int tid = threadIdx.x;
    const int lane = tid & 31;
    const int wid = tid >> 5;
    const int wm = wid & 1;          // M half
    const int wn = wid >> 1;         // N eighth (0..7 -> 32 cols)
    const int pbase = blockIdx.x * MROWS;

    float acc[MT][4][4];
#pragma unroll
    for (int mt = 0; mt < MT; mt++)
#pragma unroll
        for (int nt = 0; nt < 4; nt++)
#pragma unroll
            for (int e = 0; e < 4; e++) acc[mt][nt][e] = 0.0f;

    // ---- producer (A from pre-split fp16 h, B from pre-swizzled images) ----
    auto produce = [&](int it) {
        const uint32_t dst = sb + (it & 1) * SMB;
        const int kc = it * KCH;
#pragma unroll
        for (int t = 0; t < (MROWS * 8 + 511) / 512; t++) {
            int G = tid + t * 512;
            if ((MROWS * 8) % 512 == 0 || G < MROWS * 8) {
                int r = G >> 3, cg = G & 7;
                size_t so = (size_t)(pbase + r) * KP + kc + cg * 8;
                uint32_t d = dst + SW128(r * 128 + cg * 16);
                cp16(d, hhin + so);
                cp16(d + 16384, hlin + so);
            }
        }
        const __half* bh = g_Bh + (size_t)it * 16384;
        const __half* bl = g_Bl + (size_t)it * 16384;
#pragma unroll
        for (int t = 0; t < 4; t++) {
            int G = tid + t * 512;
            cp16(dst + 32768 + G * 16, bh + G * 8);
            cp16(dst + 65536 + G * 16, bl + G * 8);
        }
        CP_COMMIT();
    };

    produce(0);

    // per-lane ldmatrix address components
    const int arow = (lane >> 3 & 1) * 8 + (lane & 7);
    const int acol = (lane >> 4) * 16;
    const int brow = (lane >> 4) * 8 + (lane & 7);
    const int bcol = (lane >> 3 & 1) * 16;

    for (int i = 0; i < NITER; i++) {
        CP_WAIT0();
        __syncthreads();
        if (i + 1 < NITER) produce(i + 1);
        const uint32_t s0 = sb + (i & 1) * SMB;

#pragma unroll
        for (int ks = 0; ks < 4; ks++) {
            uint32_t fa[MT][4], fb[2][4];
            uint32_t ad[MT], bd[2];
#pragma unroll
            for (int mt = 0; mt < MT; mt++) {
                int row = wm * (MT * 16) + mt * 16 + arow;
                ad[mt] = s0 + SW128(row * 128 + ks * 32 + acol);
            }
#pragma unroll
            for (int ntp = 0; ntp < 2; ntp++) {
                int row = wn * 32 + ntp * 16 + brow;
                bd[ntp] = s0 + 32768 + SW128(row * 128 + ks * 32 + bcol);
            }
            // pass 1: A_hi * B_hi
#pragma unroll
            for (int mt = 0; mt < MT; mt++) LDSM4(fa[mt], ad[mt]);
#pragma unroll
            for (int ntp = 0; ntp < 2; ntp++) LDSM4(fb[ntp], bd[ntp]);
#pragma unroll
            for (int mt = 0; mt < MT; mt++)
#pragma unroll
                for (int nt = 0; nt < 4; nt++) {
                    int np = nt >> 1, sel = (nt & 1) * 2;
                    MMA16816(acc[mt][nt], fa[mt], fb[np][sel], fb[np][sel + 1]);
                }
            // pass 2: A_hi * B_lo
#pragma unroll
            for (int ntp = 0; ntp < 2; ntp++) LDSM4(fb[ntp], bd[ntp] + 32768);
#pragma unroll
            for (int mt = 0; mt < MT; mt++)
#pragma unroll
                for (int nt = 0; nt < 4; nt++) {
                    int np = nt >> 1, sel = (nt & 1) * 2;
                    MMA16816(acc[mt][nt], fa[mt], fb[np][sel], fb[np][sel + 1]);
                }
            // pass 3: A_lo * B_hi
#pragma unroll
            for (int mt = 0; mt < MT; mt++) LDSM4(fa[mt], ad[mt] + 16384);
#pragma unroll
            for (int ntp = 0; ntp < 2; ntp++) LDSM4(fb[ntp], bd[ntp]);
#pragma unroll
            for (int mt = 0; mt < MT; mt++)
#pragma unroll
                for (int nt = 0; nt < 4; nt++) {
                    int np = nt >> 1, sel = (nt & 1) * 2;
                    MMA16816(acc[mt][nt], fa[mt], fb[np][sel], fb[np][sel + 1]);
                }
        }
    }

    // ---- epilogue: bias + tanh; optional fp32 and fp16-split outputs ----
#pragma unroll
    for (int mt = 0; mt < MT; mt++) {
#pragma unroll
        for (int nt = 0; nt < 4; nt++) {
            int p0 = pbase + wm * (MT * 16) + mt * 16 + (lane >> 2);
            int nn = wn * 32 + nt * 8 + 2 * (lane & 3);
#pragma unroll
            for (int hf = 0; hf < 2; hf++) {
                int p = p0 + hf * 8;
                size_t o = (size_t)p * D + nn;
                float2 bv = *reinterpret_cast<const float2*>(bias + o);
                float v0 = tanhf(acc[mt][nt][hf * 2 + 0] + bv.x);
                float v1 = tanhf(acc[mt][nt][hf * 2 + 1] + bv.y);
                if (WRITE32) {
                    float2 ov = {v0, v1};
                    *reinterpret_cast<float2*>(h32 + o) = ov;
                }
                if (WRITE16) {
                    __half h0 = __float2half_rn(v0);
                    __half h1 = __float2half_rn(v1);
                    *reinterpret_cast<__half2*>(hho + o) = __halves2half2(h0, h1);
                    __half l0 = __float2half_rn(v0 - __half2float(h0));
                    __half l1 = __float2half_rn(v1 - __half2float(h1));
                    *reinterpret_cast<__half2*>(hlo + o) = __halves2half2(l0, l1);
                }
            }
        }
    }
}

// ---------------- small-level kernel (fp32, K-split across warps) --------
#define PT 8
__global__ void __launch_bounds__(256)
gemm_small_kernel(const float* __restrict__ hin, const float* __restrict__ bias,
                  float* __restrict__ hout, int n_par) {
    __shared__ float uv_s[PT][K2];
    __shared__ float part[8][PT][32];

    const int tid = threadIdx.x;
    const int pbase = blockIdx.x * PT;
    const int col0 = blockIdx.y * 32;
    const float C13 = 1.0f / 3.0f;
    const float C23 = 2.0f / 3.0f;

#pragma unroll
    for (int i = 0; i < PT * K2 / 256; i++) {
        int idx = tid + i * 256;
        int lp = idx >> 9;
        int k = idx & 511;
        int c = k & 255;
        int p = pbase + lp;
        float v = 0.0f;
        if (p < n_par) {
            const float* cb = hin + ((size_t)p * 4) * D + c;
            if (k < D) v = cb[0] + C23 * cb[D] + C13 * cb[2 * D];
            else       v = C13 * cb[D] + C23 * cb[2 * D] + cb[3 * D];
        }
        uv_s[lp][k] = v;
    }
    __syncthreads();

    const int w = tid >> 5;
    const int lane = tid & 31;
    const float* wp = g_WcT + (size_t)(w * 64) * D + col0 + lane;

    float acc[PT];
#pragma unroll
    for (int p = 0; p < PT; p++) acc[p] = 0.0f;

#pragma unroll 8
    for (int k = 0; k < 64; k++) {
        float wv = wp[(size_t)k * D];
        int kg = w * 64 + k;
#pragma unroll
        for (int p = 0; p < PT; p++)
            acc[p] = fmaf(uv_s[p][kg], wv, acc[p]);
    }
#pragma unroll
    for (int p = 0; p < PT; p++) part[w][p][lane] = acc[p];
    __syncthreads();

    int p = tid >> 5;
    int pg = pbase + p;
    if (pg < n_par) {
        float s = 0.0f;
#pragma unroll
        for (int w2 = 0; w2 < 8; w2++) s += part[w2][p][lane];
        int n = col0 + lane;
        hout[(size_t)pg * D + n] = tanhf(s + bias[(size_t)pg * D + n]);
    }
}

// ---------------- host launcher ------------------------------------------
extern "C" void kernel_launch(void* const* d_in, const int* in_sizes, int n_in,
                              void* d_out, int out_size) {
    const float* vectors = (const float*)d_in[0];
    const float* Wl      = (const float*)d_in[1];
    const float* Wr      = (const float*)d_in[2];
    float* out = (float*)d_out;

    static bool attr_set = false;
    if (!attr_set) {
        cudaFuncSetAttribute(gemm_tc_kernel<4, false, true>,
                             cudaFuncAttributeMaxDynamicSharedMemorySize, 2 * SMB);
        cudaFuncSetAttribute(gemm_tc_kernel<1, false, true>,
                             cudaFuncAttributeMaxDynamicSharedMemorySize, 2 * SMB);
        cudaFuncSetAttribute(gemm_tc_kernel<1, true, false>,
                             cudaFuncAttributeMaxDynamicSharedMemorySize, 2 * SMB);
        attr_set = true;
    }

    int offsets[LEVELS];
    int s = 0, sz = 1;
    for (int l = 0; l < LEVELS; l++) { offsets[l] = s; s += sz; sz *= 4; }

    float* hbuf;
    cudaGetSymbolAddress((void**)&hbuf, g_h);
    float* hb[2] = {hbuf, hbuf + (size_t)MAX_PAR * D};

    __half *phh, *phl, *lhh, *lhl;
    cudaGetSymbolAddress((void**)&phh, g_ph_h);
    cudaGetSymbolAddress((void**)&phl, g_ph_l);
    cudaGetSymbolAddress((void**)&lhh, g_lh_h);
    cudaGetSymbolAddress((void**)&lhl, g_lh_l);
    __half* ph_h[2] = {phh, phh + (size_t)MAX_PAR * D};
    __half* ph_l[2] = {phl, phl + (size_t)MAX_PAR * D};

    pack_w_kernel<<<dim3(8, 8, 2), dim3(32, 8)>>>(Wl, Wr);
    pack_b_kernel<<<1024, 256>>>(Wl, Wr);
    leaf_split_kernel<<<NLEAF * D / (256 * 8), 256>>>(
        vectors + (size_t)offsets[LEVELS - 1] * D);

    const __half* hh_in = lhh;
    const __half* hl_in = lhl;
    const float* h32_in = nullptr;
    int n_par = 1 << (2 * (LEVELS - 2));   // 16384

    for (int l = LEVELS - 2; l >= 0; l--) {
        const float* bias = vectors + (size_t)offsets[l] * D;
        if (n_par >= 1024) {
            if (l == 7) {
                gemm_tc_kernel<4, false, true><<<n_par / 128, 512, 2 * SMB>>>(
                    hh_in, hl_in, bias, nullptr, ph_h[l & 1], ph_l[l & 1]);
            } else if (l == 6) {
                gemm_tc_kernel<1, false, true><<<n_par / 32, 512, 2 * SMB>>>(
                    hh_in, hl_in, bias, nullptr, ph_h[l & 1], ph_l[l & 1]);
            } else {  // l == 5: last TC level -> fp32 for small levels
                gemm_tc_kernel<1, true, false><<<n_par / 32, 512, 2 * SMB>>>(
                    hh_in, hl_in, bias, hb[l & 1], nullptr, nullptr);
                h32_in = hb[l & 1];
            }
            hh_in = ph_h[l & 1];
            hl_in = ph_l[l & 1];
        } else {
            float* hout = (l == 0) ? out : hb[l & 1];
            dim3 grid((n_par + PT - 1) / PT, 8);
            gemm_small_kernel<<<grid, 256>>>(h32_in, bias, hout, n_par);
            h32_in = hout;
        }
        n_par >>= 2;
    }
}

// round 17
// speedup vs baseline: 1.3192x; 1.1061x over previous
#include <cuda_runtime.h>
#include <cuda_fp16.h>
#include <math.h>
#include <stdint.h>

// ---------------- problem constants ----------------
#define D       256
#define K2      512           // small-kernel contraction (u|v form)
#define KP      1024          // TC contraction: 4 children x 256
#define KCH     32            // K per TC iteration
#define NITER   (KP / KCH)    // 32
#define LEVELS  9
#define MAX_PAR 16384
#define NLEAF   65536

// ---------------- device scratch (no cudaMalloc allowed) ----------------
__device__ float  g_h[2][(size_t)MAX_PAR * D];          // fp32 ping-pong (small levels)
__device__ float  g_WcT[(size_t)K2 * D];                // fp32 W for small kernel
__device__ __half g_ph_h[2][(size_t)MAX_PAR * D];       // TC-output h split hi (ping-pong)
__device__ __half g_ph_l[2][(size_t)MAX_PAR * D];       // TC-output h split lo
__device__ __half g_Bh[(size_t)NITER * 256 * KCH];      // pre-swizzled B-hi iter images
__device__ __half g_Bl[(size_t)NITER * 256 * KCH];      // pre-swizzled B-lo iter images

// ---------------- helpers ----------------
__device__ __forceinline__ uint32_t smem_u32(const void* p) {
    uint32_t a;
    asm("{ .reg .u64 t; cvta.to.shared.u64 t, %1; cvt.u32.u64 %0, t; }"
        : "=r"(a) : "l"(p));
    return a;
}
#define SW64(o) ((o) ^ (((o) >> 3) & 0x30))

__device__ __forceinline__ void cp16(uint32_t dst, const void* src) {
    asm volatile("cp.async.cg.shared.global [%0], [%1], 16;"
                 :: "r"(dst), "l"(src) : "memory");
}
#define CP_COMMIT() asm volatile("cp.async.commit_group;" ::: "memory")
#define CP_WAIT0()  asm volatile("cp.async.wait_group 0;" ::: "memory")

#define LDSM4(r, addr) \
    asm volatile("ldmatrix.sync.aligned.m8n8.x4.shared.b16 {%0,%1,%2,%3}, [%4];" \
        : "=r"((r)[0]), "=r"((r)[1]), "=r"((r)[2]), "=r"((r)[3]) : "r"(addr))

#define MMA16816(c, a, b0_, b1_) \
    asm volatile("mma.sync.aligned.m16n8k16.row.col.f32.f16.f16.f32 " \
        "{%0,%1,%2,%3}, {%4,%5,%6,%7}, {%8,%9}, {%0,%1,%2,%3};" \
        : "+f"((c)[0]), "+f"((c)[1]), "+f"((c)[2]), "+f"((c)[3]) \
        : "r"((a)[0]), "r"((a)[1]), "r"((a)[2]), "r"((a)[3]), "r"(b0_), "r"(b1_))

// ---------------- pack W (transposed fp32) for small kernel ----------------
__global__ void __launch_bounds__(256)
pack_w_kernel(const float* __restrict__ Wl, const float* __restrict__ Wr) {
    __shared__ float t[32][33];
    const float* src = blockIdx.z ? Wr : Wl;
    int i0 = blockIdx.x * 32;
    int k0 = blockIdx.y * 32;
    int lx = threadIdx.x, ly = threadIdx.y;
#pragma unroll
    for (int r = 0; r < 4; r++)
        t[ly + 8 * r][lx] = src[(size_t)(i0 + ly + 8 * r) * D + k0 + lx];
    __syncthreads();
#pragma unroll
    for (int r = 0; r < 4; r++) {
        int k = k0 + ly + 8 * r + (blockIdx.z ? D : 0);
        g_WcT[(size_t)k * D + i0 + lx] = t[lx][ly + 8 * r];
    }
}

// ---------------- pack coefficient-folded B (fp16 hi/lo, pre-swizzled) ----
// Bt[n][kk] = lc_j*Wl[n][k] + rc_j*Wr[n][k], kk = j*256+k.
// NITER images: [256 rows(n)][32 cols] fp16, 64B rows, SW64-swizzled, 16KB.
__global__ void __launch_bounds__(256)
pack_b_kernel(const float* __restrict__ Wl, const float* __restrict__ Wr) {
    int gid = blockIdx.x * 256 + threadIdx.x;     // over 256*1024
    int n = gid >> 10;
    int kk = gid & 1023;
    int j = kk >> 8;
    int k = kk & 255;
    const float C13 = 1.0f / 3.0f, C23 = 2.0f / 3.0f;
    float lc = (j == 0) ? 1.0f : (j == 1) ? C23 : (j == 2) ? C13 : 0.0f;
    float rc = (j == 0) ? 0.0f : (j == 1) ? C13 : (j == 2) ? C23 : 1.0f;
    float w = lc * Wl[(size_t)n * D + k] + rc * Wr[(size_t)n * D + k];
    __half hi = __float2half_rn(w);
    __half lo = __float2half_rn(w - __half2float(hi));
    int it = kk >> 5;
    int c = kk & 31;
    size_t off = (size_t)it * 8192 + (SW64(n * 64 + c * 2) >> 1);
    g_Bh[off] = hi;
    g_Bl[off] = lo;
}

// ---------------- TC GEMM: 3xFP16 split via mma.sync ----------------
// CTA: MROWS(=MT*32) parents x 128 cols, 256 threads (8 warps: 2M x 4N).
// K=1024, chunks of 32, double-buffered; 2 CTAs/SM co-resident.
// buffer layout: Ahi 8K | Alo 8K | Bhi 8K | Blo 8K = 32K; x2 = 64K.
#define SMB 32768

template<int MT, bool LEAF, bool WRITE32, bool WRITE16>
__global__ void __launch_bounds__(256, 2)
gemm_tc_kernel(const __half* __restrict__ hhin, const __half* __restrict__ hlin,
               const float* __restrict__ leafv,
               const float* __restrict__ bias,
               float* __restrict__ h32, __half* __restrict__ hho,
               __half* __restrict__ hlo) {
    constexpr int MROWS = MT * 32;
    constexpr int AG = MROWS * 4;           // A granules (8 halves) per chunk
    constexpr int AT = (AG + 255) / 256;    // A granules per thread
    extern __shared__ __align__(1024) char smem[];
    const uint32_t sb = smem_u32(smem);
    const int tid = threadIdx.x;
    const int lane = tid & 31;
    const int wid = tid >> 5;
    const int wm = wid & 1;          // M half
    const int wn = wid >> 1;         // N quarter (32 cols)
    const int pbase = blockIdx.x * MROWS;
    const int ncol0 = blockIdx.y * 128;

    float acc[MT][4][4];
#pragma unroll
    for (int mt = 0; mt < MT; mt++)
#pragma unroll
        for (int nt = 0; nt < 4; nt++)
#pragma unroll
            for (int e = 0; e < 4; e++) acc[mt][nt][e] = 0.0f;

    // B producer: verbatim copy of pre-swizzled image rows [ncol0, ncol0+128)
    auto produce_b = [&](int it) {
        const uint32_t dst = sb + (it & 1) * SMB + 16384;
        const __half* bh = g_Bh + (size_t)it * 8192 + ncol0 * 32;
        const __half* bl = g_Bl + (size_t)it * 8192 + ncol0 * 32;
#pragma unroll
        for (int t = 0; t < 2; t++) {
            int G = tid + t * 256;
            cp16(dst + G * 16, bh + G * 8);
            cp16(dst + 8192 + G * 16, bl + G * 8);
        }
    };
    // A producer (non-leaf): cp.async from pre-split fp16 h
    auto produce_a = [&](int it) {
        const uint32_t dst = sb + (it & 1) * SMB;
        const int kc = it * KCH;
#pragma unroll
        for (int t = 0; t < AT; t++) {
            int G = tid + t * 256;
            if (AG % 256 == 0 || G < AG) {
                int r = G >> 2, cg = G & 3;
                size_t so = (size_t)(pbase + r) * KP + kc + cg * 8;
                uint32_t d = dst + SW64(r * 64 + cg * 16);
                cp16(d, hhin + so);
                cp16(d + 8192, hlin + so);
            }
        }
    };
    // A leaf stage: LDG fp32 into regs (latency hidden by compute)
    float4 stg[AT][2];
    auto leaf_load = [&](int it) {
        const int kc = it * KCH;
#pragma unroll
        for (int t = 0; t < AT; t++) {
            int G = tid + t * 256;
            int r = G >> 2, cg = G & 3;
            int kk = kc + cg * 8;
            const float* s = leafv +
                ((size_t)((pbase + r) * 4 + (kk >> 8))) * D + (kk & 255);
            stg[t][0] = *reinterpret_cast<const float4*>(s);
            stg[t][1] = *reinterpret_cast<const float4*>(s + 4);
        }
    };
    // A leaf store: split regs -> smem hi/lo
    auto leaf_store = [&](int it) {
        const uint32_t dst = sb + (it & 1) * SMB;
#pragma unroll
        for (int t = 0; t < AT; t++) {
            int G = tid + t * 256;
            int r = G >> 2, cg = G & 3;
            float xs[8] = {stg[t][0].x, stg[t][0].y, stg[t][0].z, stg[t][0].w,
                           stg[t][1].x, stg[t][1].y, stg[t][1].z, stg[t][1].w};
            union { __half h[8]; uint4 u; } hh, hl;
#pragma unroll
            for (int e = 0; e < 8; e++) {
                __half hi = __float2half_rn(xs[e]);
                hh.h[e] = hi;
                hl.h[e] = __float2half_rn(xs[e] - __half2float(hi));
            }
            uint32_t d = dst + SW64(r * 64 + cg * 16);
            *reinterpret_cast<uint4*>(smem + (d - sb)) = hh.u;
            *reinterpret_cast<uint4*>(smem + (d - sb) + 8192) = hl.u;
        }
    };

    // prologue: stage chunk 0.
    // NOTE: produce_a(0) MUST precede CP_COMMIT — wait_group only covers
    // committed groups (this ordering bug caused the R16 rel_err=0.11).
    if (!LEAF) produce_a(0);
    produce_b(0);
    CP_COMMIT();
    if (LEAF) { leaf_load(0); leaf_store(0); }

    // per-lane ldmatrix address components
    const int arow = (lane >> 3 & 1) * 8 + (lane & 7);
    const int acol = (lane >> 4) * 16;
    const int brow = (lane >> 4) * 8 + (lane & 7);
    const int bcol = (lane >> 3 & 1) * 16;

    for (int i = 0; i < NITER; i++) {
        CP_WAIT0();
        __syncthreads();
        if (i + 1 < NITER) {
            produce_b(i + 1);
            if (!LEAF) produce_a(i + 1);
            CP_COMMIT();
            if (LEAF) leaf_load(i + 1);
        }
        const uint32_t s0 = sb + (i & 1) * SMB;

#pragma unroll
        for (int ks = 0; ks < 2; ks++) {
            uint32_t fa[MT][4], fb[2][4];
            uint32_t ad[MT], bd[2];
#pragma unroll
            for (int mt = 0; mt < MT; mt++) {
                int row = wm * (MT * 16) + mt * 16 + arow;
                ad[mt] = s0 + SW64(row * 64 + ks * 32 + acol);
            }
#pragma unroll
            for (int ntp = 0; ntp < 2; ntp++) {
                int row = wn * 32 + ntp * 16 + brow;
                bd[ntp] = s0 + 16384 + SW64(row * 64 + ks * 32 + bcol);
            }
            // pass 1: A_hi * B_hi
#pragma unroll
            for (int mt = 0; mt < MT; mt++) LDSM4(fa[mt], ad[mt]);
#pragma unroll
            for (int ntp = 0; ntp < 2; ntp++) LDSM4(fb[ntp], bd[ntp]);
#pragma unroll
            for (int mt = 0; mt < MT; mt++)
#pragma unroll
                for (int nt = 0; nt < 4; nt++) {
                    int np = nt >> 1, sel = (nt & 1) * 2;
                    MMA16816(acc[mt][nt], fa[mt], fb[np][sel], fb[np][sel + 1]);
                }
            // pass 2: A_hi * B_lo
#pragma unroll
            for (int ntp = 0; ntp < 2; ntp++) LDSM4(fb[ntp], bd[ntp] + 8192);
#pragma unroll
            for (int mt = 0; mt < MT; mt++)
#pragma unroll
                for (int nt = 0; nt < 4; nt++) {
                    int np = nt >> 1, sel = (nt & 1) * 2;
                    MMA16816(acc[mt][nt], fa[mt], fb[np][sel], fb[np][sel + 1]);
                }
            // pass 3: A_lo * B_hi
#pragma unroll
            for (int mt = 0; mt < MT; mt++) LDSM4(fa[mt], ad[mt] + 8192);
#pragma unroll
            for (int ntp = 0; ntp < 2; ntp++) LDSM4(fb[ntp], bd[ntp]);
#pragma unroll
            for (int mt = 0; mt < MT; mt++)
#pragma unroll
                for (int nt = 0; nt < 4; nt++) {
                    int np = nt >> 1, sel = (nt & 1) * 2;
                    MMA16816(acc[mt][nt], fa[mt], fb[np][sel], fb[np][sel + 1]);
                }
        }

        if (LEAF && i + 1 < NITER) leaf_store(i + 1);
    }

    // ---- epilogue: bias + tanh; optional fp32 and fp16-split outputs ----
#pragma unroll
    for (int mt = 0; mt < MT; mt++) {
#pragma unroll
        for (int nt = 0; nt < 4; nt++) {
            int p0 = pbase + wm * (MT * 16) + mt * 16 + (lane >> 2);
            int nn = ncol0 + wn * 32 + nt * 8 + 2 * (lane & 3);
#pragma unroll
            for (int hf = 0; hf < 2; hf++) {
                int p = p0 + hf * 8;
                size_t o = (size_t)p * D + nn;
                float2 bv = *reinterpret_cast<const float2*>(bias + o);
                float v0 = tanhf(acc[mt][nt][hf * 2 + 0] + bv.x);
                float v1 = tanhf(acc[mt][nt][hf * 2 + 1] + bv.y);
                if (WRITE32) {
                    float2 ov = {v0, v1};
                    *reinterpret_cast<float2*>(h32 + o) = ov;
                }
                if (WRITE16) {
                    __half h0 = __float2half_rn(v0);
                    __half h1 = __float2half_rn(v1);
                    *reinterpret_cast<__half2*>(hho + o) = __halves2half2(h0, h1);
                    __half l0 = __float2half_rn(v0 - __half2float(h0));
                    __half l1 = __float2half_rn(v1 - __half2float(h1));
                    *reinterpret_cast<__half2*>(hlo + o) = __halves2half2(l0, l1);
                }
            }
        }
    }
}

// ---------------- small-level kernel (fp32, K-split across warps) --------
#define PT 8
__global__ void __launch_bounds__(256)
gemm_small_kernel(const float* __restrict__ hin, const float* __restrict__ bias,
                  float* __restrict__ hout, int n_par) {
    __shared__ float uv_s[PT][K2];
    __shared__ float part[8][PT][32];

    const int tid = threadIdx.x;
    const int pbase = blockIdx.x * PT;
    const int col0 = blockIdx.y * 32;
    const float C13 = 1.0f / 3.0f;
    const float C23 = 2.0f / 3.0f;

#pragma unroll
    for (int i = 0; i < PT * K2 / 256; i++) {
        int idx = tid + i * 256;
        int lp = idx >> 9;
        int k = idx & 511;
        int c = k & 255;
        int p = pbase + lp;
        float v = 0.0f;
        if (p < n_par) {
            const float* cb = hin + ((size_t)p * 4) * D + c;
            if (k < D) v = cb[0] + C23 * cb[D] + C13 * cb[2 * D];
            else       v = C13 * cb[D] + C23 * cb[2 * D] + cb[3 * D];
        }
        uv_s[lp][k] = v;
    }
    __syncthreads();

    const int w = tid >> 5;
    const int lane = tid & 31;
    const float* wp = g_WcT + (size_t)(w * 64) * D + col0 + lane;

    float acc[PT];
#pragma unroll
    for (int p = 0; p < PT; p++) acc[p] = 0.0f;

#pragma unroll 8
    for (int k = 0; k < 64; k++) {
        float wv = wp[(size_t)k * D];
        int kg = w * 64 + k;
#pragma unroll
        for (int p = 0; p < PT; p++)
            acc[p] = fmaf(uv_s[p][kg], wv, acc[p]);
    }
#pragma unroll
    for (int p = 0; p < PT; p++) part[w][p][lane] = acc[p];
    __syncthreads();

    int p = tid >> 5;
    int pg = pbase + p;
    if (pg < n_par) {
        float s = 0.0f;
#pragma unroll
        for (int w2 = 0; w2 < 8; w2++) s += part[w2][p][lane];
        int n = col0 + lane;
        hout[(size_t)pg * D + n] = tanhf(s + bias[(size_t)pg * D + n]);
    }
}

// ---------------- host launcher ------------------------------------------
extern "C" void kernel_launch(void* const* d_in, const int* in_sizes, int n_in,
                              void* d_out, int out_size) {
    const float* vectors = (const float*)d_in[0];
    const float* Wl      = (const float*)d_in[1];
    const float* Wr      = (const float*)d_in[2];
    float* out = (float*)d_out;

    static bool attr_set = false;
    if (!attr_set) {
        cudaFuncSetAttribute(gemm_tc_kernel<4, true, false, true>,
                             cudaFuncAttributeMaxDynamicSharedMemorySize, 2 * SMB);
        cudaFuncSetAttribute(gemm_tc_kernel<1, false, false, true>,
                             cudaFuncAttributeMaxDynamicSharedMemorySize, 2 * SMB);
        cudaFuncSetAttribute(gemm_tc_kernel<1, false, true, false>,
                             cudaFuncAttributeMaxDynamicSharedMemorySize, 2 * SMB);
        attr_set = true;
    }

    int offsets[LEVELS];
    int s = 0, sz = 1;
    for (int l = 0; l < LEVELS; l++) { offsets[l] = s; s += sz; sz *= 4; }

    float* hbuf;
    cudaGetSymbolAddress((void**)&hbuf, g_h);
    float* hb[2] = {hbuf, hbuf + (size_t)MAX_PAR * D};

    __half *phh, *phl;
    cudaGetSymbolAddress((void**)&phh, g_ph_h);
    cudaGetSymbolAddress((void**)&phl, g_ph_l);
    __half* ph_h[2] = {phh, phh + (size_t)MAX_PAR * D};
    __half* ph_l[2] = {phl, phl + (size_t)MAX_PAR * D};

    pack_w_kernel<<<dim3(8, 8, 2), dim3(32, 8)>>>(Wl, Wr);
    pack_b_kernel<<<1024, 256>>>(Wl, Wr);

    const float* leafv = vectors + (size_t)offsets[LEVELS - 1] * D;
    const __half* hh_in = nullptr;
    const __half* hl_in = nullptr;
    const float* h32_in = nullptr;
    int n_par = 1 << (2 * (LEVELS - 2));   // 16384

    for (int l = LEVELS - 2; l >= 0; l--) {
        const float* bias = vectors + (size_t)offsets[l] * D;
        if (n_par >= 1024) {
            if (l == 7) {      // leaf-fused, 128-row tiles, write fp16 split
                gemm_tc_kernel<4, true, false, true>
                    <<<dim3(n_par / 128, 2), 256, 2 * SMB>>>(
                    nullptr, nullptr, leafv, bias,
                    nullptr, ph_h[l & 1], ph_l[l & 1]);
            } else if (l == 6) {  // 32-row tiles for full-chip spread
                gemm_tc_kernel<1, false, false, true>
                    <<<dim3(n_par / 32, 2), 256, 2 * SMB>>>(
                    hh_in, hl_in, nullptr, bias,
                    nullptr, ph_h[l & 1], ph_l[l & 1]);
            } else {           // l == 5: last TC level -> fp32 for small levels
                gemm_tc_kernel<1, false, true, false>
                    <<<dim3(n_par / 32, 2), 256, 2 * SMB>>>(
                    hh_in, hl_in, nullptr, bias,
                    hb[l & 1], nullptr, nullptr);
                h32_in = hb[l & 1];
            }
            hh_in = ph_h[l & 1];
            hl_in = ph_l[l & 1];
        } else {
            float* hout = (l == 0) ? out : hb[l & 1];
            dim3 grid((n_par + PT - 1) / PT, 8);
            gemm_small_kernel<<<grid, 256>>>(h32_in, bias, hout, n_par);
            h32_in = hout;
        }
        n_par >>= 2;
    }
}